// round 3
// baseline (speedup 1.0000x reference)
#include <cuda_runtime.h>
#include <cuda_bf16.h>
#include <math.h>
#include <stdint.h>

// Problem constants
#define NTOK   2048       // B*N
#define DDIM   1024
#define QDIM   2048       // 2*H*KD
#define NHEAD  8
#define KDIM   128
#define NKEYS  256
#define TOPK   16

// -------- scratch (device globals; no runtime allocation) --------
__device__ float g_cs[DDIM];          // per-col scale  = gamma * rstd
__device__ float g_cb[DDIM];          // per-col bias   = beta - mean*gamma*rstd
__device__ float g_qbias[QDIM];       // c @ Wq
__device__ float g_q[(size_t)NTOK * QDIM];      // 16 MB query matrix
__device__ float g_scores[(size_t)NTOK * NHEAD * TOPK];
__device__ int   g_sidx[(size_t)NTOK * NHEAD * TOPK];

// ---------------- packed f32x2 helpers ----------------
__device__ __forceinline__ unsigned long long pk2(float lo, float hi) {
    unsigned long long r;
    asm("mov.b64 %0, {%1,%2};" : "=l"(r) : "f"(lo), "f"(hi));
    return r;
}
__device__ __forceinline__ unsigned long long fma2(unsigned long long a,
                                                   unsigned long long b,
                                                   unsigned long long c) {
    unsigned long long d;
    asm("fma.rn.f32x2 %0, %1, %2, %3;" : "=l"(d) : "l"(a), "l"(b), "l"(c));
    return d;
}
__device__ __forceinline__ void unpk2(unsigned long long v, float& lo, float& hi) {
    asm("mov.b64 {%0,%1}, %2;" : "=f"(lo), "=f"(hi) : "l"(v));
}

// ---------------- kernel 1: BN stats -> fold into scale/bias ----------------
// 32 blocks x 256 threads; block handles 32 columns; (tx=col lane, ty=row slice)
__global__ void bn_stats_kernel(const float* __restrict__ X,
                                const float* __restrict__ gamma,
                                const float* __restrict__ beta) {
    int tx = threadIdx.x & 31, ty = threadIdx.x >> 5;   // ty in 0..7
    int col = blockIdx.x * 32 + tx;
    float s = 0.f, ss = 0.f;
    for (int r = ty; r < NTOK; r += 8) {
        float v = X[(size_t)r * DDIM + col];
        s += v; ss += v * v;
    }
    __shared__ float sh[2][8][33];
    sh[0][ty][tx] = s; sh[1][ty][tx] = ss;
    __syncthreads();
    if (ty == 0) {
        float ts = 0.f, tss = 0.f;
#pragma unroll
        for (int i = 0; i < 8; i++) { ts += sh[0][i][tx]; tss += sh[1][i][tx]; }
        float mean = ts * (1.0f / NTOK);
        float var  = tss * (1.0f / NTOK) - mean * mean;
        float rstd = rsqrtf(var + 1e-5f);
        float sc   = gamma[col] * rstd;
        g_cs[col]  = sc;
        g_cb[col]  = beta[col] - mean * sc;
    }
}

// ---------------- kernel 2: qbias = cb @ Wq ----------------
// 32 blocks x 256 threads: 64 j-cols per block, 4 d-slices
__global__ void qbias_kernel(const float* __restrict__ Wq) {
    int tid = threadIdx.x;
    int jx = tid & 63, ds = tid >> 6;
    int j = blockIdx.x * 64 + jx;
    float acc = 0.f;
    int d0 = ds * 256;
    for (int d = d0; d < d0 + 256; d++)
        acc += g_cb[d] * Wq[(size_t)d * QDIM + j];
    __shared__ float sh[4][64];
    sh[ds][jx] = acc;
    __syncthreads();
    if (ds == 0) g_qbias[j] = sh[0][jx] + sh[1][jx] + sh[2][jx] + sh[3][jx];
}

// ---------------- kernel 3: fp32 GEMM with packed FFMA2 ----------------
// Q[t,j] = sum_d (X[t,d]*cs[d]) * Wq[d,j] + qbias[j]
// BM=BN=128, BK=16, 256 threads, 8x8 per-thread tile (cols as 4 f32x2 pairs)
#define BM 128
#define BN 128
#define BK 16
__global__ void __launch_bounds__(256) gemm_q_kernel(const float* __restrict__ X,
                                                     const float* __restrict__ Wq) {
    __shared__ float As[BK][BM + 4];   // stride 132 floats -> 16B aligned
    __shared__ float Bs[BK][BN];
    int tid = threadIdx.x;
    int ty = tid >> 4, tx = tid & 15;
    int bm = blockIdx.y * BM;
    int bn = blockIdx.x * BN;

    unsigned long long acc[8][4];
#pragma unroll
    for (int i = 0; i < 8; i++)
#pragma unroll
        for (int j = 0; j < 4; j++) acc[i][j] = 0ULL;

    for (int k0 = 0; k0 < DDIM; k0 += BK) {
        // stage A (128 tokens x 16 d), scaled by cs, stored transposed
#pragma unroll
        for (int l = 0; l < 2; l++) {
            int idx = tid + l * 256;
            int row = idx >> 2, q4 = idx & 3;
            float4 v = *(const float4*)&X[(size_t)(bm + row) * DDIM + k0 + q4 * 4];
            float4 s = *(const float4*)&g_cs[k0 + q4 * 4];
            As[q4 * 4 + 0][row] = v.x * s.x;
            As[q4 * 4 + 1][row] = v.y * s.y;
            As[q4 * 4 + 2][row] = v.z * s.z;
            As[q4 * 4 + 3][row] = v.w * s.w;
        }
        // stage B (16 d x 128 j)
#pragma unroll
        for (int l = 0; l < 2; l++) {
            int idx = tid + l * 256;
            int row = idx >> 5, c4 = idx & 31;
            float4 v = *(const float4*)&Wq[(size_t)(k0 + row) * QDIM + bn + c4 * 4];
            *(float4*)&Bs[row][c4 * 4] = v;
        }
        __syncthreads();
#pragma unroll
        for (int k = 0; k < BK; k++) {
            float a[8], b[8];
            *(float4*)&a[0] = *(const float4*)&As[k][ty * 8];
            *(float4*)&a[4] = *(const float4*)&As[k][ty * 8 + 4];
            *(float4*)&b[0] = *(const float4*)&Bs[k][tx * 8];
            *(float4*)&b[4] = *(const float4*)&Bs[k][tx * 8 + 4];
            unsigned long long bp[4];
#pragma unroll
            for (int j = 0; j < 4; j++) bp[j] = pk2(b[2 * j], b[2 * j + 1]);
#pragma unroll
            for (int i = 0; i < 8; i++) {
                unsigned long long ad = pk2(a[i], a[i]);
#pragma unroll
                for (int j = 0; j < 4; j++) acc[i][j] = fma2(ad, bp[j], acc[i][j]);
            }
        }
        __syncthreads();
    }
    // epilogue: + qbias, store
#pragma unroll
    for (int i = 0; i < 8; i++) {
        int row = bm + ty * 8 + i;
#pragma unroll
        for (int j = 0; j < 4; j++) {
            float lo, hi;
            unpk2(acc[i][j], lo, hi);
            int col = bn + tx * 8 + 2 * j;
            float2 o;
            o.x = lo + g_qbias[col];
            o.y = hi + g_qbias[col + 1];
            *(float2*)&g_q[(size_t)row * QDIM + col] = o;
        }
    }
}

// ---------------- kernel 4: sim + two-stage top-16 ----------------
// grid (64 token-groups, 8 heads), 256 threads, TT=32 tokens per block
#define TT 32
__global__ void __launch_bounds__(256) sim_topk_kernel(const float* __restrict__ keys) {
    extern __shared__ float smem[];
    float* q_sh    = smem;                        // TT*128
    float* sim_sh  = q_sh + TT * 128;             // TT*256
    float* keys_sh = sim_sh + TT * 256;           // 32*129
    float* sx_sh   = keys_sh + 32 * 129;          // TT*16
    int*   ix_sh   = (int*)(sx_sh + TT * 16);     // TT*16
    float* sy_sh   = (float*)(ix_sh + TT * 16);   // TT*16
    int*   iy_sh   = (int*)(sy_sh + TT * 16);     // TT*16

    int tid = threadIdx.x;
    int lane = tid & 31, w = tid >> 5;            // 8 warps
    int h = blockIdx.y;
    int t0 = blockIdx.x * TT;

    for (int p = 0; p < 2; p++) {
        // stage q tile: TT x 128
        for (int i = tid; i < TT * 32; i += 256) {
            int row = i >> 5, c4 = i & 31;
            float4 v = *(const float4*)&g_q[(size_t)(t0 + row) * QDIM + p * 1024 + h * KDIM + c4 * 4];
            *(float4*)&q_sh[row * 128 + c4 * 4] = v;
        }
        __syncthreads();
        // 8 chunks of 32 keys
        for (int kc = 0; kc < 8; kc++) {
            for (int i = tid; i < 32 * 32; i += 256) {
                int kr = i >> 5, c4 = i & 31;
                float4 v = *(const float4*)&keys[(size_t)((h * NKEYS + kc * 32 + kr) * 2 + p) * KDIM + c4 * 4];
                float* dst = &keys_sh[kr * 129 + c4 * 4];
                dst[0] = v.x; dst[1] = v.y; dst[2] = v.z; dst[3] = v.w;
            }
            __syncthreads();
            // warp w -> tokens w*4..w*4+3, lane = key within chunk
            int tb = w * 4;
            float a0 = 0.f, a1 = 0.f, a2 = 0.f, a3 = 0.f;
            const float* kr = &keys_sh[lane * 129];
#pragma unroll 4
            for (int kd = 0; kd < 128; kd++) {
                float kv = kr[kd];
                a0 += q_sh[(tb + 0) * 128 + kd] * kv;
                a1 += q_sh[(tb + 1) * 128 + kd] * kv;
                a2 += q_sh[(tb + 2) * 128 + kd] * kv;
                a3 += q_sh[(tb + 3) * 128 + kd] * kv;
            }
            int kcol = kc * 32 + lane;
            sim_sh[(tb + 0) * 256 + kcol] = a0;
            sim_sh[(tb + 1) * 256 + kcol] = a1;
            sim_sh[(tb + 2) * 256 + kcol] = a2;
            sim_sh[(tb + 3) * 256 + kcol] = a3;
            __syncthreads();
        }
        // top-16 of 256 per token (warp-cooperative iterative argmax)
        for (int rep = 0; rep < 4; rep++) {
            int t = w * 4 + rep;
            float v[8];
#pragma unroll
            for (int j = 0; j < 8; j++) v[j] = sim_sh[t * 256 + j * 32 + lane];
            for (int it = 0; it < TOPK; it++) {
                float bv = v[0]; int bj = 0;
#pragma unroll
                for (int j = 1; j < 8; j++) if (v[j] > bv) { bv = v[j]; bj = j; }
                int bi = bj * 32 + lane;
#pragma unroll
                for (int off = 16; off; off >>= 1) {
                    float ov = __shfl_down_sync(0xffffffffu, bv, off);
                    int   oi = __shfl_down_sync(0xffffffffu, bi, off);
                    if (ov > bv || (ov == bv && oi < bi)) { bv = ov; bi = oi; }
                }
                bv = __shfl_sync(0xffffffffu, bv, 0);
                bi = __shfl_sync(0xffffffffu, bi, 0);
                if ((bi & 31) == lane) v[bi >> 5] = -INFINITY;
                if (lane == 0) {
                    if (p == 0) { sx_sh[t * TOPK + it] = bv; ix_sh[t * TOPK + it] = bi; }
                    else        { sy_sh[t * TOPK + it] = bv; iy_sh[t * TOPK + it] = bi; }
                }
            }
        }
        __syncthreads();
    }
    // cartesian merge: 256 combos -> top-16
    for (int rep = 0; rep < 4; rep++) {
        int t = w * 4 + rep;
        float v[8];
#pragma unroll
        for (int j = 0; j < 8; j++) {
            int c = j * 32 + lane;
            v[j] = sx_sh[t * TOPK + (c >> 4)] + sy_sh[t * TOPK + (c & 15)];
        }
        for (int it = 0; it < TOPK; it++) {
            float bv = v[0]; int bj = 0;
#pragma unroll
            for (int j = 1; j < 8; j++) if (v[j] > bv) { bv = v[j]; bj = j; }
            int bi = bj * 32 + lane;
#pragma unroll
            for (int off = 16; off; off >>= 1) {
                float ov = __shfl_down_sync(0xffffffffu, bv, off);
                int   oi = __shfl_down_sync(0xffffffffu, bi, off);
                if (ov > bv || (ov == bv && oi < bi)) { bv = ov; bi = oi; }
            }
            bv = __shfl_sync(0xffffffffu, bv, 0);
            bi = __shfl_sync(0xffffffffu, bi, 0);
            if ((bi & 31) == lane) v[bi >> 5] = -INFINITY;
            if (lane == 0) {
                int expert = ix_sh[t * TOPK + (bi >> 4)] * NKEYS + iy_sh[t * TOPK + (bi & 15)];
                size_t o = ((size_t)(t0 + t) * NHEAD + h) * TOPK + it;
                g_scores[o] = bv;
                g_sidx[o]   = expert;
            }
        }
    }
}

// ---------------- kernel 5: expert gather / down-dot / act / up-accumulate ----------------
// one block per token, 512 threads (16 warps)
__global__ void __launch_bounds__(512) expert_kernel(const float* __restrict__ X,
                                                     const float* __restrict__ down_w,
                                                     const float* __restrict__ up_w,
                                                     float* __restrict__ out) {
    __shared__ float xin[DDIM];
    __shared__ float hsh[128];
    __shared__ int   isha[128];
    __shared__ float ssh[128];
    int t = blockIdx.x, tid = threadIdx.x;
    *(float2*)&xin[tid * 2] = *(const float2*)&X[(size_t)t * DDIM + tid * 2];
    if (tid < 128) {
        isha[tid] = g_sidx[(size_t)t * 128 + tid];
        ssh[tid]  = g_scores[(size_t)t * 128 + tid];
    }
    __syncthreads();

    int w = tid >> 5, lane = tid & 31;
    const float4* xin4 = (const float4*)xin;
    // down: warp w handles experts w, w+16, ...
    for (int e = w; e < 128; e += 16) {
        const float4* wr = (const float4*)(down_w + (size_t)isha[e] * DDIM);
        float acc = 0.f;
#pragma unroll
        for (int i = 0; i < 8; i++) {
            float4 a = wr[lane + i * 32];
            float4 b = xin4[lane + i * 32];
            acc += a.x * b.x + a.y * b.y + a.z * b.z + a.w * b.w;
        }
#pragma unroll
        for (int off = 16; off; off >>= 1) acc += __shfl_down_sync(0xffffffffu, acc, off);
        if (lane == 0) hsh[e] = acc;
    }
    __syncthreads();
    if (tid < 128) {
        float hv = hsh[tid];
        float g  = 0.5f * hv * (1.0f + erff(hv * 0.70710678118654752f));  // exact GELU
        float sg = 1.0f / (1.0f + expf(-ssh[tid]));
        hsh[tid] = g * sg;
    }
    __syncthreads();
    // up: each thread owns 2 output columns
    int c = tid * 2;
    float accx = 0.f, accy = 0.f;
#pragma unroll 4
    for (int e = 0; e < 128; e++) {
        float2 uw = *(const float2*)(up_w + (size_t)isha[e] * DDIM + c);
        float hv = hsh[e];
        accx += hv * uw.x;
        accy += hv * uw.y;
    }
    float2 o; o.x = accx; o.y = accy;
    *(float2*)&out[(size_t)t * DDIM + c] = o;
}

// ---------------- launch ----------------
extern "C" void kernel_launch(void* const* d_in, const int* in_sizes, int n_in,
                              void* d_out, int out_size) {
    const float* X      = (const float*)d_in[0];
    const float* gamma  = (const float*)d_in[1];
    const float* beta   = (const float*)d_in[2];
    const float* Wq     = (const float*)d_in[3];
    const float* keys   = (const float*)d_in[4];
    const float* down_w = (const float*)d_in[5];
    const float* up_w   = (const float*)d_in[6];
    float* out = (float*)d_out;

    bn_stats_kernel<<<32, 256>>>(X, gamma, beta);
    qbias_kernel<<<32, 256>>>(Wq);
    gemm_q_kernel<<<dim3(QDIM / BN, NTOK / BM), 256>>>(X, Wq);

    int smem4 = (TT * 128 + TT * 256 + 32 * 129 + TT * TOPK * 4) * 4;
    cudaFuncSetAttribute(sim_topk_kernel, cudaFuncAttributeMaxDynamicSharedMemorySize, smem4);
    sim_topk_kernel<<<dim3(NTOK / TT, NHEAD), 256, smem4>>>(keys);

    expert_kernel<<<NTOK, 512>>>(X, down_w, up_w, out);
}

// round 6
// speedup vs baseline: 1.0267x; 1.0267x over previous
#include <cuda_runtime.h>
#include <cuda_bf16.h>
#include <math.h>
#include <stdint.h>

// Problem constants
#define NTOK   2048       // B*N
#define DDIM   1024
#define QDIM   2048       // 2*H*KD
#define NHEAD  8
#define KDIM   128
#define NKEYS  256
#define TOPK   16

// -------- scratch (device globals; no runtime allocation) --------
__device__ float g_cs[DDIM];          // per-col scale  = gamma * rstd
__device__ float g_cb[DDIM];          // per-col bias   = beta - mean*gamma*rstd
__device__ float g_qbias[QDIM];       // c @ Wq
__device__ float g_q[(size_t)NTOK * QDIM];      // 16 MB query matrix
__device__ float g_scores[(size_t)NTOK * NHEAD * TOPK];
__device__ int   g_sidx[(size_t)NTOK * NHEAD * TOPK];

// ---------------- packed f32x2 helpers ----------------
__device__ __forceinline__ unsigned long long pk2(float lo, float hi) {
    unsigned long long r;
    asm("mov.b64 %0, {%1,%2};" : "=l"(r) : "f"(lo), "f"(hi));
    return r;
}
__device__ __forceinline__ unsigned long long fma2(unsigned long long a,
                                                   unsigned long long b,
                                                   unsigned long long c) {
    unsigned long long d;
    asm("fma.rn.f32x2 %0, %1, %2, %3;" : "=l"(d) : "l"(a), "l"(b), "l"(c));
    return d;
}
__device__ __forceinline__ void unpk2(unsigned long long v, float& lo, float& hi) {
    asm("mov.b64 {%0,%1}, %2;" : "=f"(lo), "=f"(hi) : "l"(v));
}

// ---------------- kernel 1: BN stats -> fold into scale/bias ----------------
__global__ void bn_stats_kernel(const float* __restrict__ X,
                                const float* __restrict__ gamma,
                                const float* __restrict__ beta) {
    int tx = threadIdx.x & 31, ty = threadIdx.x >> 5;   // ty in 0..7
    int col = blockIdx.x * 32 + tx;
    float s = 0.f, ss = 0.f;
    for (int r = ty; r < NTOK; r += 8) {
        float v = X[(size_t)r * DDIM + col];
        s += v; ss += v * v;
    }
    __shared__ float sh[2][8][33];
    sh[0][ty][tx] = s; sh[1][ty][tx] = ss;
    __syncthreads();
    if (ty == 0) {
        float ts = 0.f, tss = 0.f;
#pragma unroll
        for (int i = 0; i < 8; i++) { ts += sh[0][i][tx]; tss += sh[1][i][tx]; }
        float mean = ts * (1.0f / NTOK);
        float var  = tss * (1.0f / NTOK) - mean * mean;
        float rstd = rsqrtf(var + 1e-5f);
        float sc   = gamma[col] * rstd;
        g_cs[col]  = sc;
        g_cb[col]  = beta[col] - mean * sc;
    }
}

// ---------------- kernel 2: qbias = cb @ Wq ----------------
__global__ void qbias_kernel(const float* __restrict__ Wq) {
    int tid = threadIdx.x;
    int jx = tid & 63, ds = tid >> 6;
    int j = blockIdx.x * 64 + jx;
    float acc = 0.f;
    int d0 = ds * 256;
    for (int d = d0; d < d0 + 256; d++)
        acc += g_cb[d] * Wq[(size_t)d * QDIM + j];
    __shared__ float sh[4][64];
    sh[ds][jx] = acc;
    __syncthreads();
    if (ds == 0) g_qbias[j] = sh[0][jx] + sh[1][jx] + sh[2][jx] + sh[3][jx];
}

// ---------------- kernel 3: fp32 GEMM with packed FFMA2 ----------------
#define BM 128
#define BN 128
#define BK 16
__global__ void __launch_bounds__(256) gemm_q_kernel(const float* __restrict__ X,
                                                     const float* __restrict__ Wq) {
    __shared__ float As[BK][BM + 4];
    __shared__ float Bs[BK][BN];
    int tid = threadIdx.x;
    int ty = tid >> 4, tx = tid & 15;
    int bm = blockIdx.y * BM;
    int bn = blockIdx.x * BN;

    unsigned long long acc[8][4];
#pragma unroll
    for (int i = 0; i < 8; i++)
#pragma unroll
        for (int j = 0; j < 4; j++) acc[i][j] = 0ULL;

    for (int k0 = 0; k0 < DDIM; k0 += BK) {
#pragma unroll
        for (int l = 0; l < 2; l++) {
            int idx = tid + l * 256;
            int row = idx >> 2, q4 = idx & 3;
            float4 v = *(const float4*)&X[(size_t)(bm + row) * DDIM + k0 + q4 * 4];
            float4 s = *(const float4*)&g_cs[k0 + q4 * 4];
            As[q4 * 4 + 0][row] = v.x * s.x;
            As[q4 * 4 + 1][row] = v.y * s.y;
            As[q4 * 4 + 2][row] = v.z * s.z;
            As[q4 * 4 + 3][row] = v.w * s.w;
        }
#pragma unroll
        for (int l = 0; l < 2; l++) {
            int idx = tid + l * 256;
            int row = idx >> 5, c4 = idx & 31;
            float4 v = *(const float4*)&Wq[(size_t)(k0 + row) * QDIM + bn + c4 * 4];
            *(float4*)&Bs[row][c4 * 4] = v;
        }
        __syncthreads();
#pragma unroll
        for (int k = 0; k < BK; k++) {
            float a[8], b[8];
            *(float4*)&a[0] = *(const float4*)&As[k][ty * 8];
            *(float4*)&a[4] = *(const float4*)&As[k][ty * 8 + 4];
            *(float4*)&b[0] = *(const float4*)&Bs[k][tx * 8];
            *(float4*)&b[4] = *(const float4*)&Bs[k][tx * 8 + 4];
            unsigned long long bp[4];
#pragma unroll
            for (int j = 0; j < 4; j++) bp[j] = pk2(b[2 * j], b[2 * j + 1]);
#pragma unroll
            for (int i = 0; i < 8; i++) {
                unsigned long long ad = pk2(a[i], a[i]);
#pragma unroll
                for (int j = 0; j < 4; j++) acc[i][j] = fma2(ad, bp[j], acc[i][j]);
            }
        }
        __syncthreads();
    }
#pragma unroll
    for (int i = 0; i < 8; i++) {
        int row = bm + ty * 8 + i;
#pragma unroll
        for (int j = 0; j < 4; j++) {
            float lo, hi;
            unpk2(acc[i][j], lo, hi);
            int col = bn + tx * 8 + 2 * j;
            float2 o;
            o.x = lo + g_qbias[col];
            o.y = hi + g_qbias[col + 1];
            *(float2*)&g_q[(size_t)row * QDIM + col] = o;
        }
    }
}

// ---------------- kernel 4: sim + two-stage top-16 (register-tiled rewrite) ----
// grid (64 token-groups, 8 heads), 256 threads, TT=32 tokens per block.
// smem: qt[128][32] (q transposed), kt[128][64] (key chunk transposed),
//       sim[32][256], topk scratch. 90KB -> 2 blocks/SM.
// Thread tile: 8 tokens x 1 key per 64-key chunk; token-pairs packed as f32x2.
#define TT 32
__global__ void __launch_bounds__(256) sim_topk_kernel(const float* __restrict__ keys) {
    extern __shared__ float smem[];
    float* qt     = smem;                         // 128*32  = 4096
    float* kt     = qt + 128 * 32;                // 128*64  = 8192
    float* sim_sh = kt + 128 * 64;                // 32*256  = 8192
    float* sx_sh  = sim_sh + 32 * 256;            // 32*16
    int*   ix_sh  = (int*)(sx_sh + TT * 16);
    float* sy_sh  = (float*)(ix_sh + TT * 16);
    int*   iy_sh  = (int*)(sy_sh + TT * 16);

    int tid = threadIdx.x;
    int lane = tid & 31, w = tid >> 5;            // 8 warps
    int tg = tid >> 6;                            // token group 0..3 (8 tokens each)
    int kx = tid & 63;                            // key within chunk 0..63
    int h = blockIdx.y;
    int t0 = blockIdx.x * TT;

    for (int p = 0; p < 2; p++) {
        // ---- stage qt: [kd][token], transposed ----
#pragma unroll
        for (int l = 0; l < 4; l++) {
            int i = tid + l * 256;
            int token = i & 31, kd4 = i >> 5;     // kd4 0..31
            float4 v = *(const float4*)&g_q[(size_t)(t0 + token) * QDIM + p * 1024 + h * KDIM + kd4 * 4];
            qt[(kd4 * 4 + 0) * 32 + token] = v.x;
            qt[(kd4 * 4 + 1) * 32 + token] = v.y;
            qt[(kd4 * 4 + 2) * 32 + token] = v.z;
            qt[(kd4 * 4 + 3) * 32 + token] = v.w;
        }
        __syncthreads();

        // ---- 4 chunks of 64 keys ----
        for (int c = 0; c < 4; c++) {
            // stage kt: [kd][key], transposed
#pragma unroll
            for (int l = 0; l < 8; l++) {
                int i = tid + l * 256;
                int key = i & 63, kd4 = i >> 6;   // kd4 0..31
                float4 v = *(const float4*)&keys[(size_t)((h * NKEYS + c * 64 + key) * 2 + p) * KDIM + kd4 * 4];
                kt[(kd4 * 4 + 0) * 64 + key] = v.x;
                kt[(kd4 * 4 + 1) * 64 + key] = v.y;
                kt[(kd4 * 4 + 2) * 64 + key] = v.z;
                kt[(kd4 * 4 + 3) * 64 + key] = v.w;
            }
            __syncthreads();

            // compute: 8 tokens x 1 key per thread, token pairs in f32x2
            unsigned long long acc0 = 0ULL, acc1 = 0ULL, acc2 = 0ULL, acc3 = 0ULL;
            const float* qbase = qt + tg * 8;
            const float* kbase = kt + kx;
#pragma unroll
            for (int kd = 0; kd < 128; kd++) {
                ulonglong2 A0 = *(const ulonglong2*)(qbase + kd * 32);       // tokens 0..3
                ulonglong2 A1 = *(const ulonglong2*)(qbase + kd * 32 + 4);   // tokens 4..7
                float b = kbase[kd * 64];
                unsigned long long bb = pk2(b, b);
                acc0 = fma2(A0.x, bb, acc0);
                acc1 = fma2(A0.y, bb, acc1);
                acc2 = fma2(A1.x, bb, acc2);
                acc3 = fma2(A1.y, bb, acc3);
            }
            // write sim
            int kcol = c * 64 + kx;
            float lo, hi;
            unpk2(acc0, lo, hi);
            sim_sh[(tg * 8 + 0) * 256 + kcol] = lo; sim_sh[(tg * 8 + 1) * 256 + kcol] = hi;
            unpk2(acc1, lo, hi);
            sim_sh[(tg * 8 + 2) * 256 + kcol] = lo; sim_sh[(tg * 8 + 3) * 256 + kcol] = hi;
            unpk2(acc2, lo, hi);
            sim_sh[(tg * 8 + 4) * 256 + kcol] = lo; sim_sh[(tg * 8 + 5) * 256 + kcol] = hi;
            unpk2(acc3, lo, hi);
            sim_sh[(tg * 8 + 6) * 256 + kcol] = lo; sim_sh[(tg * 8 + 7) * 256 + kcol] = hi;
            __syncthreads();
        }

        // ---- top-16 of 256 per token (warp-cooperative iterative argmax) ----
        for (int rep = 0; rep < 4; rep++) {
            int t = w * 4 + rep;
            float v[8];
#pragma unroll
            for (int j = 0; j < 8; j++) v[j] = sim_sh[t * 256 + j * 32 + lane];
            for (int it = 0; it < TOPK; it++) {
                float bv = v[0]; int bj = 0;
#pragma unroll
                for (int j = 1; j < 8; j++) if (v[j] > bv) { bv = v[j]; bj = j; }
                int bi = bj * 32 + lane;
#pragma unroll
                for (int off = 16; off; off >>= 1) {
                    float ov = __shfl_down_sync(0xffffffffu, bv, off);
                    int   oi = __shfl_down_sync(0xffffffffu, bi, off);
                    if (ov > bv || (ov == bv && oi < bi)) { bv = ov; bi = oi; }
                }
                bv = __shfl_sync(0xffffffffu, bv, 0);
                bi = __shfl_sync(0xffffffffu, bi, 0);
                if ((bi & 31) == lane) v[bi >> 5] = -INFINITY;
                if (lane == 0) {
                    if (p == 0) { sx_sh[t * TOPK + it] = bv; ix_sh[t * TOPK + it] = bi; }
                    else        { sy_sh[t * TOPK + it] = bv; iy_sh[t * TOPK + it] = bi; }
                }
            }
        }
        __syncthreads();   // protect qt/sim reuse in next part
    }

    // ---- cartesian merge: 256 combos -> top-16 ----
    for (int rep = 0; rep < 4; rep++) {
        int t = w * 4 + rep;
        float v[8];
#pragma unroll
        for (int j = 0; j < 8; j++) {
            int c = j * 32 + lane;
            v[j] = sx_sh[t * TOPK + (c >> 4)] + sy_sh[t * TOPK + (c & 15)];
        }
        for (int it = 0; it < TOPK; it++) {
            float bv = v[0]; int bj = 0;
#pragma unroll
            for (int j = 1; j < 8; j++) if (v[j] > bv) { bv = v[j]; bj = j; }
            int bi = bj * 32 + lane;
#pragma unroll
            for (int off = 16; off; off >>= 1) {
                float ov = __shfl_down_sync(0xffffffffu, bv, off);
                int   oi = __shfl_down_sync(0xffffffffu, bi, off);
                if (ov > bv || (ov == bv && oi < bi)) { bv = ov; bi = oi; }
            }
            bv = __shfl_sync(0xffffffffu, bv, 0);
            bi = __shfl_sync(0xffffffffu, bi, 0);
            if ((bi & 31) == lane) v[bi >> 5] = -INFINITY;
            if (lane == 0) {
                int expert = ix_sh[t * TOPK + (bi >> 4)] * NKEYS + iy_sh[t * TOPK + (bi & 15)];
                size_t o = ((size_t)(t0 + t) * NHEAD + h) * TOPK + it;
                g_scores[o] = bv;
                g_sidx[o]   = expert;
            }
        }
    }
}

// ---------------- kernel 5: expert gather / down-dot / act / up-accumulate ----
__global__ void __launch_bounds__(512) expert_kernel(const float* __restrict__ X,
                                                     const float* __restrict__ down_w,
                                                     const float* __restrict__ up_w,
                                                     float* __restrict__ out) {
    __shared__ float xin[DDIM];
    __shared__ float hsh[128];
    __shared__ int   isha[128];
    __shared__ float ssh[128];
    int t = blockIdx.x, tid = threadIdx.x;
    *(float2*)&xin[tid * 2] = *(const float2*)&X[(size_t)t * DDIM + tid * 2];
    if (tid < 128) {
        isha[tid] = g_sidx[(size_t)t * 128 + tid];
        ssh[tid]  = g_scores[(size_t)t * 128 + tid];
    }
    __syncthreads();

    int w = tid >> 5, lane = tid & 31;
    const float4* xin4 = (const float4*)xin;
    for (int e = w; e < 128; e += 16) {
        const float4* wr = (const float4*)(down_w + (size_t)isha[e] * DDIM);
        float acc = 0.f;
#pragma unroll
        for (int i = 0; i < 8; i++) {
            float4 a = wr[lane + i * 32];
            float4 b = xin4[lane + i * 32];
            acc += a.x * b.x + a.y * b.y + a.z * b.z + a.w * b.w;
        }
#pragma unroll
        for (int off = 16; off; off >>= 1) acc += __shfl_down_sync(0xffffffffu, acc, off);
        if (lane == 0) hsh[e] = acc;
    }
    __syncthreads();
    if (tid < 128) {
        float hv = hsh[tid];
        float g  = 0.5f * hv * (1.0f + erff(hv * 0.70710678118654752f));  // exact GELU
        float sg = 1.0f / (1.0f + expf(-ssh[tid]));
        hsh[tid] = g * sg;
    }
    __syncthreads();
    int c = tid * 2;
    float accx = 0.f, accy = 0.f;
#pragma unroll 4
    for (int e = 0; e < 128; e++) {
        float2 uw = *(const float2*)(up_w + (size_t)isha[e] * DDIM + c);
        float hv = hsh[e];
        accx += hv * uw.x;
        accy += hv * uw.y;
    }
    float2 o; o.x = accx; o.y = accy;
    *(float2*)&out[(size_t)t * DDIM + c] = o;
}

// ---------------- launch ----------------
extern "C" void kernel_launch(void* const* d_in, const int* in_sizes, int n_in,
                              void* d_out, int out_size) {
    const float* X      = (const float*)d_in[0];
    const float* gamma  = (const float*)d_in[1];
    const float* beta   = (const float*)d_in[2];
    const float* Wq     = (const float*)d_in[3];
    const float* keys   = (const float*)d_in[4];
    const float* down_w = (const float*)d_in[5];
    const float* up_w   = (const float*)d_in[6];
    float* out = (float*)d_out;

    bn_stats_kernel<<<32, 256>>>(X, gamma, beta);
    qbias_kernel<<<32, 256>>>(Wq);
    gemm_q_kernel<<<dim3(QDIM / BN, NTOK / BM), 256>>>(X, Wq);

    int smem4 = (128 * 32 + 128 * 64 + 32 * 256 + TT * TOPK * 4) * 4;
    cudaFuncSetAttribute(sim_topk_kernel, cudaFuncAttributeMaxDynamicSharedMemorySize, smem4);
    sim_topk_kernel<<<dim3(NTOK / TT, NHEAD), 256, smem4>>>(keys);

    expert_kernel<<<NTOK, 512>>>(X, down_w, up_w, out);
}

// round 7
// speedup vs baseline: 1.0919x; 1.0635x over previous
#include <cuda_runtime.h>
#include <cuda_bf16.h>
#include <math.h>
#include <stdint.h>

// Problem constants
#define NTOK   2048       // B*N
#define DDIM   1024
#define QDIM   2048       // 2*H*KD
#define NHEAD  8
#define KDIM   128
#define NKEYS  256
#define TOPK   16

// -------- scratch (device globals; no runtime allocation) --------
__device__ float g_cs[DDIM];          // per-col scale  = gamma * rstd
__device__ float g_cb[DDIM];          // per-col bias   = beta - mean*gamma*rstd
__device__ float g_qbias[QDIM];       // c @ Wq
__device__ float g_q[(size_t)NTOK * QDIM];      // 16 MB query matrix
__device__ float g_scores[(size_t)NTOK * NHEAD * TOPK];
__device__ int   g_sidx[(size_t)NTOK * NHEAD * TOPK];

// ---------------- packed f32x2 helpers ----------------
__device__ __forceinline__ unsigned long long pk2(float lo, float hi) {
    unsigned long long r;
    asm("mov.b64 %0, {%1,%2};" : "=l"(r) : "f"(lo), "f"(hi));
    return r;
}
__device__ __forceinline__ unsigned long long fma2(unsigned long long a,
                                                   unsigned long long b,
                                                   unsigned long long c) {
    unsigned long long d;
    asm("fma.rn.f32x2 %0, %1, %2, %3;" : "=l"(d) : "l"(a), "l"(b), "l"(c));
    return d;
}
__device__ __forceinline__ void unpk2(unsigned long long v, float& lo, float& hi) {
    asm("mov.b64 {%0,%1}, %2;" : "=f"(lo), "=f"(hi) : "l"(v));
}

// ---------------- kernel 1: BN stats -> fold into scale/bias ----------------
__global__ void bn_stats_kernel(const float* __restrict__ X,
                                const float* __restrict__ gamma,
                                const float* __restrict__ beta) {
    int tx = threadIdx.x & 31, ty = threadIdx.x >> 5;   // ty in 0..7
    int col = blockIdx.x * 32 + tx;
    float s = 0.f, ss = 0.f;
    for (int r = ty; r < NTOK; r += 8) {
        float v = X[(size_t)r * DDIM + col];
        s += v; ss += v * v;
    }
    __shared__ float sh[2][8][33];
    sh[0][ty][tx] = s; sh[1][ty][tx] = ss;
    __syncthreads();
    if (ty == 0) {
        float ts = 0.f, tss = 0.f;
#pragma unroll
        for (int i = 0; i < 8; i++) { ts += sh[0][i][tx]; tss += sh[1][i][tx]; }
        float mean = ts * (1.0f / NTOK);
        float var  = tss * (1.0f / NTOK) - mean * mean;
        float rstd = rsqrtf(var + 1e-5f);
        float sc   = gamma[col] * rstd;
        g_cs[col]  = sc;
        g_cb[col]  = beta[col] - mean * sc;
    }
}

// ---------------- kernel 2: qbias = cb @ Wq ----------------
__global__ void qbias_kernel(const float* __restrict__ Wq) {
    int tid = threadIdx.x;
    int jx = tid & 63, ds = tid >> 6;
    int j = blockIdx.x * 64 + jx;
    float acc = 0.f;
    int d0 = ds * 256;
    for (int d = d0; d < d0 + 256; d++)
        acc += g_cb[d] * Wq[(size_t)d * QDIM + j];
    __shared__ float sh[4][64];
    sh[ds][jx] = acc;
    __syncthreads();
    if (ds == 0) g_qbias[j] = sh[0][jx] + sh[1][jx] + sh[2][jx] + sh[3][jx];
}

// ---------------- kernel 3: fp32 GEMM with packed FFMA2 ----------------
#define BM 128
#define BN 128
#define BK 16
__global__ void __launch_bounds__(256) gemm_q_kernel(const float* __restrict__ X,
                                                     const float* __restrict__ Wq) {
    __shared__ float As[BK][BM + 4];
    __shared__ float Bs[BK][BN];
    int tid = threadIdx.x;
    int ty = tid >> 4, tx = tid & 15;
    int bm = blockIdx.y * BM;
    int bn = blockIdx.x * BN;

    unsigned long long acc[8][4];
#pragma unroll
    for (int i = 0; i < 8; i++)
#pragma unroll
        for (int j = 0; j < 4; j++) acc[i][j] = 0ULL;

    for (int k0 = 0; k0 < DDIM; k0 += BK) {
#pragma unroll
        for (int l = 0; l < 2; l++) {
            int idx = tid + l * 256;
            int row = idx >> 2, q4 = idx & 3;
            float4 v = *(const float4*)&X[(size_t)(bm + row) * DDIM + k0 + q4 * 4];
            float4 s = *(const float4*)&g_cs[k0 + q4 * 4];
            As[q4 * 4 + 0][row] = v.x * s.x;
            As[q4 * 4 + 1][row] = v.y * s.y;
            As[q4 * 4 + 2][row] = v.z * s.z;
            As[q4 * 4 + 3][row] = v.w * s.w;
        }
#pragma unroll
        for (int l = 0; l < 2; l++) {
            int idx = tid + l * 256;
            int row = idx >> 5, c4 = idx & 31;
            float4 v = *(const float4*)&Wq[(size_t)(k0 + row) * QDIM + bn + c4 * 4];
            *(float4*)&Bs[row][c4 * 4] = v;
        }
        __syncthreads();
#pragma unroll
        for (int k = 0; k < BK; k++) {
            float a[8], b[8];
            *(float4*)&a[0] = *(const float4*)&As[k][ty * 8];
            *(float4*)&a[4] = *(const float4*)&As[k][ty * 8 + 4];
            *(float4*)&b[0] = *(const float4*)&Bs[k][tx * 8];
            *(float4*)&b[4] = *(const float4*)&Bs[k][tx * 8 + 4];
            unsigned long long bp[4];
#pragma unroll
            for (int j = 0; j < 4; j++) bp[j] = pk2(b[2 * j], b[2 * j + 1]);
#pragma unroll
            for (int i = 0; i < 8; i++) {
                unsigned long long ad = pk2(a[i], a[i]);
#pragma unroll
                for (int j = 0; j < 4; j++) acc[i][j] = fma2(ad, bp[j], acc[i][j]);
            }
        }
        __syncthreads();
    }
#pragma unroll
    for (int i = 0; i < 8; i++) {
        int row = bm + ty * 8 + i;
#pragma unroll
        for (int j = 0; j < 4; j++) {
            float lo, hi;
            unpk2(acc[i][j], lo, hi);
            int col = bn + tx * 8 + 2 * j;
            float2 o;
            o.x = lo + g_qbias[col];
            o.y = hi + g_qbias[col + 1];
            *(float2*)&g_q[(size_t)row * QDIM + col] = o;
        }
    }
}

// ---------------- kernel 4: sim + top-16 (reg-resident sims + REDUX topk) ----
// grid (64 token-groups, 8 heads), 256 threads = 8 warps, TT=32 tokens/block.
// Warp w owns tokens w*4..w*4+3 for GEMM *and* topk; lane owns keys
// {c*64 + lane*2, +1} per 64-key chunk c. Sims live in registers (vt[4][8]).
// smem: qt[128][32] + kt[128][64] + topk scratch = 56KB -> 3 blocks/SM.
#define TT 32

// monotonic float->uint transform for unsigned max reduction
__device__ __forceinline__ unsigned ford(float f) {
    unsigned b = __float_as_uint(f);
    return b ^ (((unsigned)((int)b >> 31)) | 0x80000000u);
}

__global__ void __launch_bounds__(256, 3) sim_topk_kernel(const float* __restrict__ keys) {
    extern __shared__ float smem[];
    float* qt    = smem;                          // 128*32 = 4096 f
    float* kt    = qt + 128 * 32;                 // 128*64 = 8192 f
    float* sx_sh = kt + 128 * 64;                 // 32*16
    int*   ix_sh = (int*)(sx_sh + TT * TOPK);
    float* sy_sh = (float*)(ix_sh + TT * TOPK);
    int*   iy_sh = (int*)(sy_sh + TT * TOPK);

    int tid = threadIdx.x;
    int lane = tid & 31, w = tid >> 5;            // 8 warps
    int h = blockIdx.y;
    int t0 = blockIdx.x * TT;

    float vt[4][8];                               // [token-in-warp][key slot]

    for (int p = 0; p < 2; p++) {
        // ---- stage qt: [kd][token] transposed ----
        __syncthreads();
#pragma unroll
        for (int l = 0; l < 4; l++) {
            int i = tid + l * 256;
            int token = i & 31, kd4 = i >> 5;
            float4 v = *(const float4*)&g_q[(size_t)(t0 + token) * QDIM + p * 1024 + h * KDIM + kd4 * 4];
            qt[(kd4 * 4 + 0) * 32 + token] = v.x;
            qt[(kd4 * 4 + 1) * 32 + token] = v.y;
            qt[(kd4 * 4 + 2) * 32 + token] = v.z;
            qt[(kd4 * 4 + 3) * 32 + token] = v.w;
        }
        __syncthreads();

        // ---- 4 chunks of 64 keys ----
#pragma unroll
        for (int c = 0; c < 4; c++) {
            // stage kt: [kd][key] transposed
#pragma unroll
            for (int l = 0; l < 8; l++) {
                int i = tid + l * 256;
                int key = i & 63, kd4 = i >> 6;
                float4 v = *(const float4*)&keys[(size_t)((h * NKEYS + c * 64 + key) * 2 + p) * KDIM + kd4 * 4];
                kt[(kd4 * 4 + 0) * 64 + key] = v.x;
                kt[(kd4 * 4 + 1) * 64 + key] = v.y;
                kt[(kd4 * 4 + 2) * 64 + key] = v.z;
                kt[(kd4 * 4 + 3) * 64 + key] = v.w;
            }
            __syncthreads();

            // compute: 4 tokens (2 f32x2 pairs) x 2 keys per lane
            const float* qb = qt + w * 4;
            const float* kb = kt + lane * 2;
            unsigned long long a00 = 0ULL, a01 = 0ULL, a10 = 0ULL, a11 = 0ULL;
#pragma unroll 8
            for (int kd = 0; kd < 128; kd++) {
                ulonglong2 qv = *(const ulonglong2*)(qb + kd * 32);   // (t0,t1),(t2,t3)
                float2 kv = *(const float2*)(kb + kd * 64);           // k0,k1
                unsigned long long k0 = pk2(kv.x, kv.x);
                unsigned long long k1 = pk2(kv.y, kv.y);
                a00 = fma2(qv.x, k0, a00);
                a01 = fma2(qv.x, k1, a01);
                a10 = fma2(qv.y, k0, a10);
                a11 = fma2(qv.y, k1, a11);
            }
            float lo, hi;
            unpk2(a00, lo, hi); vt[0][c * 2 + 0] = lo; vt[1][c * 2 + 0] = hi;
            unpk2(a01, lo, hi); vt[0][c * 2 + 1] = lo; vt[1][c * 2 + 1] = hi;
            unpk2(a10, lo, hi); vt[2][c * 2 + 0] = lo; vt[3][c * 2 + 0] = hi;
            unpk2(a11, lo, hi); vt[2][c * 2 + 1] = lo; vt[3][c * 2 + 1] = hi;
            __syncthreads();
        }

        // ---- per-token top-16 of 256 via REDUX + ballot ----
#pragma unroll
        for (int rep = 0; rep < 4; rep++) {
            int t = w * 4 + rep;
            for (int it = 0; it < TOPK; it++) {
                float lv = vt[rep][0]; int bj = 0;
#pragma unroll
                for (int j = 1; j < 8; j++)
                    if (vt[rep][j] > lv) { lv = vt[rep][j]; bj = j; }
                unsigned u = ford(lv);
                unsigned m = __reduce_max_sync(0xffffffffu, u);
                unsigned msk = __ballot_sync(0xffffffffu, u == m);
                bool win = (lane == (__ffs(msk) - 1));
#pragma unroll
                for (int j = 0; j < 8; j++)
                    vt[rep][j] = (win && j == bj) ? -INFINITY : vt[rep][j];
                if (win) {
                    int key = (bj >> 1) * 64 + lane * 2 + (bj & 1);
                    if (p == 0) { sx_sh[t * TOPK + it] = lv; ix_sh[t * TOPK + it] = key; }
                    else        { sy_sh[t * TOPK + it] = lv; iy_sh[t * TOPK + it] = key; }
                }
            }
        }
        __syncwarp();
    }

    // ---- cartesian merge: 256 combos -> top-16 (same warp owns its tokens) ----
#pragma unroll
    for (int rep = 0; rep < 4; rep++) {
        int t = w * 4 + rep;
        float v[8];
#pragma unroll
        for (int j = 0; j < 8; j++) {
            int cc = j * 32 + lane;
            v[j] = sx_sh[t * TOPK + (cc >> 4)] + sy_sh[t * TOPK + (cc & 15)];
        }
        for (int it = 0; it < TOPK; it++) {
            float lv = v[0]; int bj = 0;
#pragma unroll
            for (int j = 1; j < 8; j++)
                if (v[j] > lv) { lv = v[j]; bj = j; }
            unsigned u = ford(lv);
            unsigned m = __reduce_max_sync(0xffffffffu, u);
            unsigned msk = __ballot_sync(0xffffffffu, u == m);
            bool win = (lane == (__ffs(msk) - 1));
#pragma unroll
            for (int j = 0; j < 8; j++)
                v[j] = (win && j == bj) ? -INFINITY : v[j];
            if (win) {
                int bi = bj * 32 + lane;
                int expert = ix_sh[t * TOPK + (bi >> 4)] * NKEYS + iy_sh[t * TOPK + (bi & 15)];
                size_t o = ((size_t)(t0 + t) * NHEAD + h) * TOPK + it;
                g_scores[o] = lv;
                g_sidx[o]   = expert;
            }
        }
    }
}

// ---------------- kernel 5: expert gather / down-dot / act / up-accumulate ----
__global__ void __launch_bounds__(512) expert_kernel(const float* __restrict__ X,
                                                     const float* __restrict__ down_w,
                                                     const float* __restrict__ up_w,
                                                     float* __restrict__ out) {
    __shared__ float xin[DDIM];
    __shared__ float hsh[128];
    __shared__ int   isha[128];
    __shared__ float ssh[128];
    int t = blockIdx.x, tid = threadIdx.x;
    *(float2*)&xin[tid * 2] = *(const float2*)&X[(size_t)t * DDIM + tid * 2];
    if (tid < 128) {
        isha[tid] = g_sidx[(size_t)t * 128 + tid];
        ssh[tid]  = g_scores[(size_t)t * 128 + tid];
    }
    __syncthreads();

    int w = tid >> 5, lane = tid & 31;
    const float4* xin4 = (const float4*)xin;
    for (int e = w; e < 128; e += 16) {
        const float4* wr = (const float4*)(down_w + (size_t)isha[e] * DDIM);
        float acc = 0.f;
#pragma unroll
        for (int i = 0; i < 8; i++) {
            float4 a = wr[lane + i * 32];
            float4 b = xin4[lane + i * 32];
            acc += a.x * b.x + a.y * b.y + a.z * b.z + a.w * b.w;
        }
#pragma unroll
        for (int off = 16; off; off >>= 1) acc += __shfl_down_sync(0xffffffffu, acc, off);
        if (lane == 0) hsh[e] = acc;
    }
    __syncthreads();
    if (tid < 128) {
        float hv = hsh[tid];
        float g  = 0.5f * hv * (1.0f + erff(hv * 0.70710678118654752f));  // exact GELU
        float sg = 1.0f / (1.0f + expf(-ssh[tid]));
        hsh[tid] = g * sg;
    }
    __syncthreads();
    int c = tid * 2;
    float accx = 0.f, accy = 0.f;
#pragma unroll 4
    for (int e = 0; e < 128; e++) {
        float2 uw = *(const float2*)(up_w + (size_t)isha[e] * DDIM + c);
        float hv = hsh[e];
        accx += hv * uw.x;
        accy += hv * uw.y;
    }
    float2 o; o.x = accx; o.y = accy;
    *(float2*)&out[(size_t)t * DDIM + c] = o;
}

// ---------------- launch ----------------
extern "C" void kernel_launch(void* const* d_in, const int* in_sizes, int n_in,
                              void* d_out, int out_size) {
    const float* X      = (const float*)d_in[0];
    const float* gamma  = (const float*)d_in[1];
    const float* beta   = (const float*)d_in[2];
    const float* Wq     = (const float*)d_in[3];
    const float* keys   = (const float*)d_in[4];
    const float* down_w = (const float*)d_in[5];
    const float* up_w   = (const float*)d_in[6];
    float* out = (float*)d_out;

    bn_stats_kernel<<<32, 256>>>(X, gamma, beta);
    qbias_kernel<<<32, 256>>>(Wq);
    gemm_q_kernel<<<dim3(QDIM / BN, NTOK / BM), 256>>>(X, Wq);

    int smem4 = (128 * 32 + 128 * 64 + 4 * TT * TOPK) * 4;
    cudaFuncSetAttribute(sim_topk_kernel, cudaFuncAttributeMaxDynamicSharedMemorySize, smem4);
    sim_topk_kernel<<<dim3(NTOK / TT, NHEAD), 256, smem4>>>(keys);

    expert_kernel<<<NTOK, 512>>>(X, down_w, up_w, out);
}

// round 12
// speedup vs baseline: 1.2026x; 1.1014x over previous
#include <cuda_runtime.h>
#include <cuda_bf16.h>
#include <math.h>
#include <stdint.h>

// Problem constants
#define NTOK   2048       // B*N
#define DDIM   1024
#define QDIM   2048       // 2*H*KD
#define NHEAD  8
#define KDIM   128
#define NKEYS  256
#define TOPK   16

// -------- scratch (device globals; no runtime allocation) --------
__device__ float g_cs[DDIM];          // per-col scale  = gamma * rstd
__device__ float g_cb[DDIM];          // per-col bias   = beta - mean*gamma*rstd
__device__ float g_qbias[QDIM];       // c @ Wq
__device__ float g_qT[(size_t)QDIM * NTOK];       // 16 MB, [feature][token]
__device__ float g_kT[(size_t)NHEAD * 2 * KDIM * NKEYS];  // 2 MB, [(h,p)][kd][key]
__device__ float g_scores[(size_t)NTOK * NHEAD * TOPK];
__device__ int   g_sidx[(size_t)NTOK * NHEAD * TOPK];

// ---------------- packed f32x2 helpers ----------------
__device__ __forceinline__ unsigned long long pk2(float lo, float hi) {
    unsigned long long r;
    asm("mov.b64 %0, {%1,%2};" : "=l"(r) : "f"(lo), "f"(hi));
    return r;
}
__device__ __forceinline__ unsigned long long fma2(unsigned long long a,
                                                   unsigned long long b,
                                                   unsigned long long c) {
    unsigned long long d;
    asm("fma.rn.f32x2 %0, %1, %2, %3;" : "=l"(d) : "l"(a), "l"(b), "l"(c));
    return d;
}
__device__ __forceinline__ void unpk2(unsigned long long v, float& lo, float& hi) {
    asm("mov.b64 {%0,%1}, %2;" : "=f"(lo), "=f"(hi) : "l"(v));
}

// ---------------- kernel 1: BN stats -> fold into scale/bias ----------------
__global__ void bn_stats_kernel(const float* __restrict__ X,
                                const float* __restrict__ gamma,
                                const float* __restrict__ beta) {
    int tx = threadIdx.x & 31, ty = threadIdx.x >> 5;   // ty in 0..7
    int col = blockIdx.x * 32 + tx;
    float s = 0.f, ss = 0.f;
    for (int r = ty; r < NTOK; r += 8) {
        float v = X[(size_t)r * DDIM + col];
        s += v; ss += v * v;
    }
    __shared__ float sh[2][8][33];
    sh[0][ty][tx] = s; sh[1][ty][tx] = ss;
    __syncthreads();
    if (ty == 0) {
        float ts = 0.f, tss = 0.f;
#pragma unroll
        for (int i = 0; i < 8; i++) { ts += sh[0][i][tx]; tss += sh[1][i][tx]; }
        float mean = ts * (1.0f / NTOK);
        float var  = tss * (1.0f / NTOK) - mean * mean;
        float rstd = rsqrtf(var + 1e-5f);
        float sc   = gamma[col] * rstd;
        g_cs[col]  = sc;
        g_cb[col]  = beta[col] - mean * sc;
    }
}

// ---------------- kernel 2: qbias = cb @ Wq ----------------
__global__ void qbias_kernel(const float* __restrict__ Wq) {
    int tid = threadIdx.x;
    int jx = tid & 63, ds = tid >> 6;
    int j = blockIdx.x * 64 + jx;
    float acc = 0.f;
    int d0 = ds * 256;
    for (int d = d0; d < d0 + 256; d++)
        acc += g_cb[d] * Wq[(size_t)d * QDIM + j];
    __shared__ float sh[4][64];
    sh[ds][jx] = acc;
    __syncthreads();
    if (ds == 0) g_qbias[j] = sh[0][jx] + sh[1][jx] + sh[2][jx] + sh[3][jx];
}

// ---------------- kernel 2b: transpose keys -> g_kT[(h,p)][kd][key] ---------
// grid (8 kd-tiles of 16, 16 hp), 256 threads
__global__ void ktrans_kernel(const float* __restrict__ keys) {
    __shared__ float t[256][17];
    int tid = threadIdx.x;
    int hp = blockIdx.y;                 // h*2 + p
    int h = hp >> 1, p = hp & 1;
    int kd0 = blockIdx.x * 16;
    // load: coalesced along kd (float4), 4 passes x 64 keys
    int kd4 = tid & 3, keyl = tid >> 2;  // keyl 0..63
#pragma unroll
    for (int pass = 0; pass < 4; pass++) {
        int key = pass * 64 + keyl;
        float4 v = *(const float4*)&keys[(size_t)((h * NKEYS + key) * 2 + p) * KDIM + kd0 + kd4 * 4];
        t[key][kd4 * 4 + 0] = v.x;
        t[key][kd4 * 4 + 1] = v.y;
        t[key][kd4 * 4 + 2] = v.z;
        t[key][kd4 * 4 + 3] = v.w;
    }
    __syncthreads();
    // store: coalesced along key
    int key4 = tid & 63, kdl = tid >> 6;
#pragma unroll
    for (int pass = 0; pass < 4; pass++) {
        int kd = pass * 4 + kdl;
        float4 o;
        o.x = t[key4 * 4 + 0][kd];
        o.y = t[key4 * 4 + 1][kd];
        o.z = t[key4 * 4 + 2][kd];
        o.w = t[key4 * 4 + 3][kd];
        *(float4*)&g_kT[(size_t)(hp * KDIM + kd0 + kd) * NKEYS + key4 * 4] = o;
    }
}

// ---------------- kernel 3: fp32 GEMM with packed FFMA2, transposed store ----
#define BM 128
#define BN 128
#define BK 16
__global__ void __launch_bounds__(256) gemm_q_kernel(const float* __restrict__ X,
                                                     const float* __restrict__ Wq) {
    __shared__ float As[BK][BM + 4];
    __shared__ float Bs[BK][BN];
    int tid = threadIdx.x;
    int ty = tid >> 4, tx = tid & 15;
    int bm = blockIdx.y * BM;
    int bn = blockIdx.x * BN;

    unsigned long long acc[8][4];
#pragma unroll
    for (int i = 0; i < 8; i++)
#pragma unroll
        for (int j = 0; j < 4; j++) acc[i][j] = 0ULL;

    for (int k0 = 0; k0 < DDIM; k0 += BK) {
#pragma unroll
        for (int l = 0; l < 2; l++) {
            int idx = tid + l * 256;
            int row = idx >> 2, q4 = idx & 3;
            float4 v = *(const float4*)&X[(size_t)(bm + row) * DDIM + k0 + q4 * 4];
            float4 s = *(const float4*)&g_cs[k0 + q4 * 4];
            As[q4 * 4 + 0][row] = v.x * s.x;
            As[q4 * 4 + 1][row] = v.y * s.y;
            As[q4 * 4 + 2][row] = v.z * s.z;
            As[q4 * 4 + 3][row] = v.w * s.w;
        }
#pragma unroll
        for (int l = 0; l < 2; l++) {
            int idx = tid + l * 256;
            int row = idx >> 5, c4 = idx & 31;
            float4 v = *(const float4*)&Wq[(size_t)(k0 + row) * QDIM + bn + c4 * 4];
            *(float4*)&Bs[row][c4 * 4] = v;
        }
        __syncthreads();
#pragma unroll
        for (int k = 0; k < BK; k++) {
            float a[8], b[8];
            *(float4*)&a[0] = *(const float4*)&As[k][ty * 8];
            *(float4*)&a[4] = *(const float4*)&As[k][ty * 8 + 4];
            *(float4*)&b[0] = *(const float4*)&Bs[k][tx * 8];
            *(float4*)&b[4] = *(const float4*)&Bs[k][tx * 8 + 4];
            unsigned long long bp[4];
#pragma unroll
            for (int j = 0; j < 4; j++) bp[j] = pk2(b[2 * j], b[2 * j + 1]);
#pragma unroll
            for (int i = 0; i < 8; i++) {
                unsigned long long ad = pk2(a[i], a[i]);
#pragma unroll
                for (int j = 0; j < 4; j++) acc[i][j] = fma2(ad, bp[j], acc[i][j]);
            }
        }
        __syncthreads();
    }
    // epilogue: + qbias, store TRANSPOSED into g_qT[feature][token]
    int row0 = bm + ty * 8;
#pragma unroll
    for (int j = 0; j < 4; j++) {
        int col0 = bn + tx * 8 + 2 * j;
        float b0 = g_qbias[col0], b1 = g_qbias[col0 + 1];
        float lo[8], hi[8];
#pragma unroll
        for (int i = 0; i < 8; i++) {
            unpk2(acc[i][j], lo[i], hi[i]);
            lo[i] += b0; hi[i] += b1;
        }
        *(float4*)&g_qT[(size_t)col0 * NTOK + row0]           = *(float4*)&lo[0];
        *(float4*)&g_qT[(size_t)col0 * NTOK + row0 + 4]       = *(float4*)&lo[4];
        *(float4*)&g_qT[(size_t)(col0 + 1) * NTOK + row0]     = *(float4*)&hi[0];
        *(float4*)&g_qT[(size_t)(col0 + 1) * NTOK + row0 + 4] = *(float4*)&hi[4];
    }
}

// ---------------- kernel 4: sim + top-16 v3 ----------------
// grid (64 token-groups, 8 heads), 256 threads = 8 warps, TT=32 tokens/block.
// Warp w owns tokens w*4..w*4+3 across ALL 256 keys:
//   lane owns keys {lane*4..+3} and {128+lane*4..+3}  (slot j -> (j>>2)*128+lane*4+(j&3))
// kd processed in quarters of 32, acc (f32x2 over token-pairs) persistent.
// smem 44KB static -> 3 blocks/SM.
#define TT 32
#define KD_T 32

__device__ __forceinline__ unsigned ford(float f) {
    unsigned b = __float_as_uint(f);
    return b ^ (((unsigned)((int)b >> 31)) | 0x80000000u);
}

__global__ void __launch_bounds__(256, 3) sim_topk_kernel() {
    __shared__ float qt[KD_T * 32];        // [kd][token]
    __shared__ float kt[KD_T * 256];       // [kd][key]
    __shared__ float sx_sh[TT * TOPK];
    __shared__ int   ix_sh[TT * TOPK];
    __shared__ float sy_sh[TT * TOPK];
    __shared__ int   iy_sh[TT * TOPK];

    int tid = threadIdx.x;
    int lane = tid & 31, w = tid >> 5;     // 8 warps
    int h = blockIdx.y;
    int t0 = blockIdx.x * TT;

    // staging decompositions
    int s_kd  = tid >> 3, s_tok4 = tid & 7;     // qt stage
    int s_kdp = tid >> 6, s_key4 = tid & 63;    // kt stage

    float vt[4][8];

    for (int p = 0; p < 2; p++) {
        unsigned long long acc[8][2];
#pragma unroll
        for (int j = 0; j < 8; j++) { acc[j][0] = 0ULL; acc[j][1] = 0ULL; }

        for (int q4 = 0; q4 < 4; q4++) {
            __syncthreads();
            // stage qt (coalesced from g_qT)
            {
                size_t f = (size_t)(p * 1024 + h * KDIM + q4 * KD_T + s_kd);
                float4 v = *(const float4*)&g_qT[f * NTOK + t0 + s_tok4 * 4];
                *(float4*)&qt[s_kd * 32 + s_tok4 * 4] = v;
            }
            // stage kt (coalesced from g_kT)
#pragma unroll
            for (int pass = 0; pass < 8; pass++) {
                int kd = pass * 4 + s_kdp;
                float4 v = *(const float4*)&g_kT[(size_t)((h * 2 + p) * KDIM + q4 * KD_T + kd) * NKEYS + s_key4 * 4];
                *(float4*)&kt[kd * 256 + s_key4 * 4] = v;
            }
            __syncthreads();

            const float* qb = qt + w * 4;
            const float* ka_b = kt + lane * 4;
            const float* kb_b = kt + 128 + lane * 4;
#pragma unroll 4
            for (int kd = 0; kd < KD_T; kd++) {
                float4 qv = *(const float4*)(qb + kd * 32);     // t0,t1,t2,t3 (broadcast)
                unsigned long long qp01 = pk2(qv.x, qv.y);
                unsigned long long qp23 = pk2(qv.z, qv.w);
                float4 ka = *(const float4*)(ka_b + kd * 256);
                float4 kb = *(const float4*)(kb_b + kd * 256);
                unsigned long long ks[8];
                ks[0] = pk2(ka.x, ka.x); ks[1] = pk2(ka.y, ka.y);
                ks[2] = pk2(ka.z, ka.z); ks[3] = pk2(ka.w, ka.w);
                ks[4] = pk2(kb.x, kb.x); ks[5] = pk2(kb.y, kb.y);
                ks[6] = pk2(kb.z, kb.z); ks[7] = pk2(kb.w, kb.w);
#pragma unroll
                for (int j = 0; j < 8; j++) {
                    acc[j][0] = fma2(qp01, ks[j], acc[j][0]);
                    acc[j][1] = fma2(qp23, ks[j], acc[j][1]);
                }
            }
        }

        // unpack sims: vt[token][slot]
#pragma unroll
        for (int j = 0; j < 8; j++) {
            unpk2(acc[j][0], vt[0][j], vt[1][j]);
            unpk2(acc[j][1], vt[2][j], vt[3][j]);
        }

        // per-token top-16 of 256 via REDUX + ballot
#pragma unroll
        for (int rep = 0; rep < 4; rep++) {
            int t = w * 4 + rep;
            for (int it = 0; it < TOPK; it++) {
                float lv = vt[rep][0]; int bj = 0;
#pragma unroll
                for (int j = 1; j < 8; j++)
                    if (vt[rep][j] > lv) { lv = vt[rep][j]; bj = j; }
                unsigned u = ford(lv);
                unsigned m = __reduce_max_sync(0xffffffffu, u);
                unsigned msk = __ballot_sync(0xffffffffu, u == m);
                bool win = (lane == (__ffs(msk) - 1));
#pragma unroll
                for (int j = 0; j < 8; j++)
                    vt[rep][j] = (win && j == bj) ? -INFINITY : vt[rep][j];
                if (win) {
                    int key = (bj >> 2) * 128 + lane * 4 + (bj & 3);
                    if (p == 0) { sx_sh[t * TOPK + it] = lv; ix_sh[t * TOPK + it] = key; }
                    else        { sy_sh[t * TOPK + it] = lv; iy_sh[t * TOPK + it] = key; }
                }
            }
        }
    }
    __syncthreads();

    // cartesian merge: 256 combos -> top-16
#pragma unroll
    for (int rep = 0; rep < 4; rep++) {
        int t = w * 4 + rep;
        float v[8];
#pragma unroll
        for (int j = 0; j < 8; j++) {
            int cc = j * 32 + lane;
            v[j] = sx_sh[t * TOPK + (cc >> 4)] + sy_sh[t * TOPK + (cc & 15)];
        }
        for (int it = 0; it < TOPK; it++) {
            float lv = v[0]; int bj = 0;
#pragma unroll
            for (int j = 1; j < 8; j++)
                if (v[j] > lv) { lv = v[j]; bj = j; }
            unsigned u = ford(lv);
            unsigned m = __reduce_max_sync(0xffffffffu, u);
            unsigned msk = __ballot_sync(0xffffffffu, u == m);
            bool win = (lane == (__ffs(msk) - 1));
#pragma unroll
            for (int j = 0; j < 8; j++)
                v[j] = (win && j == bj) ? -INFINITY : v[j];
            if (win) {
                int bi = bj * 32 + lane;
                int expert = ix_sh[t * TOPK + (bi >> 4)] * NKEYS + iy_sh[t * TOPK + (bi & 15)];
                size_t o = ((size_t)(t0 + t) * NHEAD + h) * TOPK + it;
                g_scores[o] = lv;
                g_sidx[o]   = expert;
            }
        }
    }
}

// ---------------- kernel 5: expert gather / down-dot / act / up-accumulate ----
__global__ void __launch_bounds__(512) expert_kernel(const float* __restrict__ X,
                                                     const float* __restrict__ down_w,
                                                     const float* __restrict__ up_w,
                                                     float* __restrict__ out) {
    __shared__ float xin[DDIM];
    __shared__ float hsh[128];
    __shared__ int   isha[128];
    __shared__ float ssh[128];
    int t = blockIdx.x, tid = threadIdx.x;
    *(float2*)&xin[tid * 2] = *(const float2*)&X[(size_t)t * DDIM + tid * 2];
    if (tid < 128) {
        isha[tid] = g_sidx[(size_t)t * 128 + tid];
        ssh[tid]  = g_scores[(size_t)t * 128 + tid];
    }
    __syncthreads();

    int w = tid >> 5, lane = tid & 31;
    const float4* xin4 = (const float4*)xin;
    for (int e = w; e < 128; e += 16) {
        const float4* wr = (const float4*)(down_w + (size_t)isha[e] * DDIM);
        float acc = 0.f;
#pragma unroll
        for (int i = 0; i < 8; i++) {
            float4 a = wr[lane + i * 32];
            float4 b = xin4[lane + i * 32];
            acc += a.x * b.x + a.y * b.y + a.z * b.z + a.w * b.w;
        }
#pragma unroll
        for (int off = 16; off; off >>= 1) acc += __shfl_down_sync(0xffffffffu, acc, off);
        if (lane == 0) hsh[e] = acc;
    }
    __syncthreads();
    if (tid < 128) {
        float hv = hsh[tid];
        float g  = 0.5f * hv * (1.0f + erff(hv * 0.70710678118654752f));  // exact GELU
        float sg = 1.0f / (1.0f + expf(-ssh[tid]));
        hsh[tid] = g * sg;
    }
    __syncthreads();
    int c = tid * 2;
    float accx = 0.f, accy = 0.f;
#pragma unroll 4
    for (int e = 0; e < 128; e++) {
        float2 uw = *(const float2*)(up_w + (size_t)isha[e] * DDIM + c);
        float hv = hsh[e];
        accx += hv * uw.x;
        accy += hv * uw.y;
    }
    float2 o; o.x = accx; o.y = accy;
    *(float2*)&out[(size_t)t * DDIM + c] = o;
}

// ---------------- launch ----------------
extern "C" void kernel_launch(void* const* d_in, const int* in_sizes, int n_in,
                              void* d_out, int out_size) {
    const float* X      = (const float*)d_in[0];
    const float* gamma  = (const float*)d_in[1];
    const float* beta   = (const float*)d_in[2];
    const float* Wq     = (const float*)d_in[3];
    const float* keys   = (const float*)d_in[4];
    const float* down_w = (const float*)d_in[5];
    const float* up_w   = (const float*)d_in[6];
    float* out = (float*)d_out;

    bn_stats_kernel<<<32, 256>>>(X, gamma, beta);
    qbias_kernel<<<32, 256>>>(Wq);
    ktrans_kernel<<<dim3(8, 16), 256>>>(keys);
    gemm_q_kernel<<<dim3(QDIM / BN, NTOK / BM), 256>>>(X, Wq);

    sim_topk_kernel<<<dim3(NTOK / TT, NHEAD), 256>>>();

    expert_kernel<<<NTOK, 512>>>(X, down_w, up_w, out);
}